// round 4
// baseline (speedup 1.0000x reference)
#include <cuda_runtime.h>
#include <math.h>

// ---------------------------------------------------------------------------
// MultiWaveletCross on GB300 — round 3: 3xTF32 tensor-core GEMMs
// (hi/lo split restores fp32-class accuracy; 3 MMAs per product)
// ---------------------------------------------------------------------------

#define BB 16
#define CKD 512
#define NTOK 16384

__device__ float g_QA[8388608];
__device__ float g_QB[8388608];
__device__ float g_KA[8388608];
__device__ float g_KB[8388608];
__device__ float g_DQ[4194304];
__device__ float g_DK[4194304];
__device__ float g_US[8380416];
__device__ float g_UD[8380416];
__device__ float g_VA[8388608];
__device__ float g_VB[8388608];
__device__ float2 g_QF[131072];
__device__ float2 g_KF[131072];
__device__ float2 g_OF[131072];

__device__ __forceinline__ unsigned f2tf32(float x) {
    unsigned r;
    asm("cvt.rna.tf32.f32 %0, %1;" : "=r"(r) : "f"(x));
    return r;
}

#define LDA_S 20
#define LDB_S 136

#define MMA_TF32(ACC, A0, A1, A2, A3, B0, B1)                                  \
    asm volatile(                                                              \
        "mma.sync.aligned.m16n8k8.row.col.f32.tf32.tf32.f32 "                  \
        "{%0,%1,%2,%3}, {%4,%5,%6,%7}, {%8,%9}, {%0,%1,%2,%3};"                \
        : "+f"(ACC[0]), "+f"(ACC[1]), "+f"(ACC[2]), "+f"(ACC[3])               \
        : "r"(A0), "r"(A1), "r"(A2), "r"(A3), "r"(B0), "r"(B1))

__device__ __forceinline__ void split_store(unsigned* h, unsigned* l,
                                            int idx, float v) {
    unsigned hb = f2tf32(v);
    h[idx] = hb;
    l[idx] = f2tf32(v - __uint_as_float(hb));
}

// C[M,512] = A[M,512] @ W[512,512] + bias, 3xTF32.
// CTA tile 128x128, 8 warps (2x4), warp tile 64x32, KB=16 single-buffered
// with register prefetch.
__global__ __launch_bounds__(256) void gemm_tf32(
    const float* __restrict__ A, const float* __restrict__ W,
    const float* __restrict__ bias, float* __restrict__ C)
{
    __shared__ unsigned As_h[128 * LDA_S], As_l[128 * LDA_S];
    __shared__ unsigned Bs_h[16 * LDB_S], Bs_l[16 * LDB_S];

    const int tid = threadIdx.x;
    const int wid = tid >> 5, lane = tid & 31;
    const int bm = blockIdx.y * 128, bn = blockIdx.x * 128;
    const int wm = (wid >> 2) * 64;
    const int wn = (wid & 3) * 32;
    const int lr = lane >> 2;
    const int lc = lane & 3;

    float acc[4][4][4];
#pragma unroll
    for (int mi = 0; mi < 4; mi++)
#pragma unroll
        for (int ni = 0; ni < 4; ni++)
#pragma unroll
            for (int r = 0; r < 4; r++) acc[mi][ni][r] = 0.f;

    const int a_i0 = tid, a_i1 = tid + 256;
    const int ar0 = a_i0 >> 2, ac0 = (a_i0 & 3) * 4;
    const int ar1 = a_i1 >> 2, ac1 = (a_i1 & 3) * 4;
    const int br0 = a_i0 >> 5, bc0 = (a_i0 & 31) * 4;
    const int br1 = a_i1 >> 5, bc1 = (a_i1 & 31) * 4;

    float4 av0, av1, bv0, bv1;
    av0 = *(const float4*)(A + (size_t)(bm + ar0) * 512 + ac0);
    av1 = *(const float4*)(A + (size_t)(bm + ar1) * 512 + ac1);
    bv0 = *(const float4*)(W + (size_t)br0 * 512 + bn + bc0);
    bv1 = *(const float4*)(W + (size_t)br1 * 512 + bn + bc1);

    for (int kb = 0; kb < 32; kb++) {
        // store current tile (hi/lo split)
        split_store(As_h, As_l, ar0 * LDA_S + ac0 + 0, av0.x);
        split_store(As_h, As_l, ar0 * LDA_S + ac0 + 1, av0.y);
        split_store(As_h, As_l, ar0 * LDA_S + ac0 + 2, av0.z);
        split_store(As_h, As_l, ar0 * LDA_S + ac0 + 3, av0.w);
        split_store(As_h, As_l, ar1 * LDA_S + ac1 + 0, av1.x);
        split_store(As_h, As_l, ar1 * LDA_S + ac1 + 1, av1.y);
        split_store(As_h, As_l, ar1 * LDA_S + ac1 + 2, av1.z);
        split_store(As_h, As_l, ar1 * LDA_S + ac1 + 3, av1.w);
        split_store(Bs_h, Bs_l, br0 * LDB_S + bc0 + 0, bv0.x);
        split_store(Bs_h, Bs_l, br0 * LDB_S + bc0 + 1, bv0.y);
        split_store(Bs_h, Bs_l, br0 * LDB_S + bc0 + 2, bv0.z);
        split_store(Bs_h, Bs_l, br0 * LDB_S + bc0 + 3, bv0.w);
        split_store(Bs_h, Bs_l, br1 * LDB_S + bc1 + 0, bv1.x);
        split_store(Bs_h, Bs_l, br1 * LDB_S + bc1 + 1, bv1.y);
        split_store(Bs_h, Bs_l, br1 * LDB_S + bc1 + 2, bv1.z);
        split_store(Bs_h, Bs_l, br1 * LDB_S + bc1 + 3, bv1.w);
        __syncthreads();

        // prefetch next K-block into registers (overlaps with MMA below)
        if (kb < 31) {
            int k0n = (kb + 1) * 16;
            av0 = *(const float4*)(A + (size_t)(bm + ar0) * 512 + k0n + ac0);
            av1 = *(const float4*)(A + (size_t)(bm + ar1) * 512 + k0n + ac1);
            bv0 = *(const float4*)(W + (size_t)(k0n + br0) * 512 + bn + bc0);
            bv1 = *(const float4*)(W + (size_t)(k0n + br1) * 512 + bn + bc1);
        }

#pragma unroll
        for (int k8 = 0; k8 < 2; k8++) {
            unsigned ah[4][4], al[4][4], bh[4][2], bl[4][2];
#pragma unroll
            for (int mi = 0; mi < 4; mi++) {
                int rb = wm + mi * 16;
                int cb = k8 * 8;
                int i00 = (rb + lr) * LDA_S + cb + lc;
                int i10 = (rb + lr + 8) * LDA_S + cb + lc;
                ah[mi][0] = As_h[i00];     al[mi][0] = As_l[i00];
                ah[mi][1] = As_h[i10];     al[mi][1] = As_l[i10];
                ah[mi][2] = As_h[i00 + 4]; al[mi][2] = As_l[i00 + 4];
                ah[mi][3] = As_h[i10 + 4]; al[mi][3] = As_l[i10 + 4];
            }
#pragma unroll
            for (int ni = 0; ni < 4; ni++) {
                int nb = wn + ni * 8 + lr;
                int j0 = (k8 * 8 + lc) * LDB_S + nb;
                int j1 = (k8 * 8 + 4 + lc) * LDB_S + nb;
                bh[ni][0] = Bs_h[j0]; bl[ni][0] = Bs_l[j0];
                bh[ni][1] = Bs_h[j1]; bl[ni][1] = Bs_l[j1];
            }
#pragma unroll
            for (int mi = 0; mi < 4; mi++)
#pragma unroll
                for (int ni = 0; ni < 4; ni++) {
                    MMA_TF32(acc[mi][ni], ah[mi][0], ah[mi][1], ah[mi][2], ah[mi][3],
                             bl[ni][0], bl[ni][1]);
                    MMA_TF32(acc[mi][ni], al[mi][0], al[mi][1], al[mi][2], al[mi][3],
                             bh[ni][0], bh[ni][1]);
                    MMA_TF32(acc[mi][ni], ah[mi][0], ah[mi][1], ah[mi][2], ah[mi][3],
                             bh[ni][0], bh[ni][1]);
                }
        }
        __syncthreads();
    }

#pragma unroll
    for (int mi = 0; mi < 4; mi++) {
#pragma unroll
        for (int ni = 0; ni < 4; ni++) {
            int col = bn + wn + ni * 8 + 2 * lc;
            float2 bv = *(const float2*)(bias + col);
            int r0 = bm + wm + mi * 16 + lr;
            float2 o0 = make_float2(acc[mi][ni][0] + bv.x, acc[mi][ni][1] + bv.y);
            float2 o1 = make_float2(acc[mi][ni][2] + bv.x, acc[mi][ni][3] + bv.y);
            *(float2*)(C + (size_t)r0 * 512 + col) = o0;
            *(float2*)(C + (size_t)(r0 + 8) * 512 + col) = o1;
        }
    }
}

// ---------------------------------------------------------------------------
// Wavelet step
// ---------------------------------------------------------------------------
__global__ __launch_bounds__(256) void wavelet_kernel(
    const float* __restrict__ x, const float* __restrict__ ecd,
    const float* __restrict__ ecs, float* __restrict__ od,
    float* __restrict__ os, int Lh)
{
    __shared__ float wd[16][8], ws_[16][8];
    int tid = threadIdx.x;
    if (tid < 128)       wd[tid >> 3][tid & 7] = ecd[tid];
    else if (tid < 256)  { int t = tid - 128; ws_[t >> 3][t & 7] = ecs[t]; }
    __syncthreads();

    long idx = (long)blockIdx.x * 256 + tid;
    long total = (long)BB * Lh * 64;
    if (idx >= total) return;
    int c = (int)(idx & 63);
    long bt = idx >> 6;
    int t2 = (int)(bt % Lh);
    int b = (int)(bt / Lh);

    const float* p0 = x + ((long)(b * 2 * Lh + 2 * t2)) * CKD + c * 8;
    float a[16];
    *(float4*)(a)      = *(const float4*)(p0);
    *(float4*)(a + 4)  = *(const float4*)(p0 + 4);
    *(float4*)(a + 8)  = *(const float4*)(p0 + CKD);
    *(float4*)(a + 12) = *(const float4*)(p0 + CKD + 4);

    float rd[8], rs[8];
#pragma unroll
    for (int kk = 0; kk < 8; kk++) { rd[kk] = 0.f; rs[kk] = 0.f; }
#pragma unroll
    for (int j = 0; j < 16; j++)
#pragma unroll
        for (int kk = 0; kk < 8; kk++) {
            rd[kk] += a[j] * wd[j][kk];
            rs[kk] += a[j] * ws_[j][kk];
        }
    float* pd = od + ((long)(b * Lh + t2)) * CKD + c * 8;
    float* ps = os + ((long)(b * Lh + t2)) * CKD + c * 8;
    *(float4*)(pd)     = *(float4*)(rd);
    *(float4*)(pd + 4) = *(float4*)(rd + 4);
    *(float4*)(ps)     = *(float4*)(rs);
    *(float4*)(ps + 4) = *(float4*)(rs + 4);
}

// ---------------------------------------------------------------------------
// Reconstruction step
// ---------------------------------------------------------------------------
__global__ __launch_bounds__(256) void recon_kernel(
    const float* __restrict__ vin, const float* __restrict__ us,
    const float* __restrict__ ud, const float* __restrict__ rce,
    const float* __restrict__ rco, float* __restrict__ vout, int Lv)
{
    __shared__ float we[16][8], wo[16][8];
    int tid = threadIdx.x;
    if (tid < 128)       we[tid >> 3][tid & 7] = rce[tid];
    else if (tid < 256)  { int t = tid - 128; wo[t >> 3][t & 7] = rco[t]; }
    __syncthreads();

    long idx = (long)blockIdx.x * 256 + tid;
    long total = (long)BB * Lv * 64;
    if (idx >= total) return;
    int c = (int)(idx & 63);
    long bt = idx >> 6;
    int t = (int)(bt % Lv);
    int b = (int)(bt / Lv);

    long base = ((long)(b * Lv + t)) * CKD + c * 8;
    float a[16];
#pragma unroll
    for (int j = 0; j < 8; j++) a[j] = vin[base + j] + us[base + j];
    *(float4*)(a + 8)  = *(const float4*)(ud + base);
    *(float4*)(a + 12) = *(const float4*)(ud + base + 4);

    float re[8], ro[8];
#pragma unroll
    for (int kk = 0; kk < 8; kk++) { re[kk] = 0.f; ro[kk] = 0.f; }
#pragma unroll
    for (int j = 0; j < 16; j++)
#pragma unroll
        for (int kk = 0; kk < 8; kk++) {
            re[kk] += a[j] * we[j][kk];
            ro[kk] += a[j] * wo[j][kk];
        }
    float* pe = vout + ((long)(b * 2 * Lv + 2 * t)) * CKD + c * 8;
    *(float4*)(pe)           = *(float4*)(re);
    *(float4*)(pe + 4)       = *(float4*)(re + 4);
    *(float4*)(pe + CKD)     = *(float4*)(ro);
    *(float4*)(pe + CKD + 4) = *(float4*)(ro + 4);
}

// ---------------------------------------------------------------------------
// rfft (first m modes)
// ---------------------------------------------------------------------------
__global__ __launch_bounds__(256) void rfft_kernel(
    const float* __restrict__ x, float2* __restrict__ F, int L, int m)
{
    __shared__ float twc[512], tws[512];
    __shared__ float tile[64][64];
    int tid = threadIdx.x;
    int ec = blockIdx.x;
    int b = blockIdx.y;

    for (int i = tid; i < L; i += 256) {
        float th = 6.2831853071795864f * (float)i / (float)L;
        float s, c; sincosf(th, &s, &c);
        twc[i] = c; tws[i] = s;
    }

    int eh = tid >> 2;
    int xg = tid & 3;
    float ar[4] = {0.f, 0.f, 0.f, 0.f}, ai[4] = {0.f, 0.f, 0.f, 0.f};

    for (int t0 = 0; t0 < L; t0 += 64) {
        int tc = L - t0 < 64 ? L - t0 : 64;
        __syncthreads();
        for (int i = tid; i < tc * 64; i += 256) {
            int tt = i >> 6, el = i & 63;
            tile[tt][el] = x[((long)(b * L + t0 + tt)) * CKD + ec * 64 + el];
        }
        __syncthreads();
        for (int tt = 0; tt < tc; tt++) {
            float v = tile[tt][eh];
            int t = t0 + tt;
#pragma unroll
            for (int j = 0; j < 4; j++) {
                int xx = xg + j * 4;
                int id = (xx * t) & (L - 1);
                ar[j] += v * twc[id];
                ai[j] -= v * tws[id];
            }
        }
    }
    int e = ec * 8 + (eh >> 3), h = eh & 7;
    float2* dst = F + ((long)((b * 8 + h) * 64 + e)) * 16;
#pragma unroll
    for (int j = 0; j < 4; j++) {
        int xx = xg + j * 4;
        if (xx < m) dst[xx] = make_float2(ar[j], ai[j]);
    }
}

// ---------------------------------------------------------------------------
// attn
// ---------------------------------------------------------------------------
__global__ __launch_bounds__(256) void attn_kernel(
    const float2* __restrict__ QF, const float2* __restrict__ KF,
    float2* __restrict__ OF, int m)
{
    __shared__ float2 qf[1024], kf[1024], S[256];
    int bh = blockIdx.x, tid = threadIdx.x;
    const float2* qsrc = QF + (long)bh * 1024;
    const float2* ksrc = KF + (long)bh * 1024;
    for (int i = tid; i < 1024; i += 256) { qf[i] = qsrc[i]; kf[i] = ksrc[i]; }
    __syncthreads();

    for (int s = tid; s < m * m; s += 256) {
        int xx = s / m, yy = s - xx * m;
        float re = 0.f, im = 0.f;
#pragma unroll 8
        for (int e = 0; e < 64; e++) {
            float2 qv = qf[e * 16 + xx], kv = kf[e * 16 + yy];
            re += qv.x * kv.x - qv.y * kv.y;
            im += qv.x * kv.y + qv.y * kv.x;
        }
        float X = 2.f * re, Y = 2.f * im, orr, oii;
        if (fabsf(X) > 20.f) {
            orr = copysignf(1.f, X); oii = 0.f;
        } else {
            float ex = expf(X), enx = 1.f / ex;
            float sh = 0.5f * (ex - enx), ch = 0.5f * (ex + enx);
            float sy, cy; sincosf(Y, &sy, &cy);
            float den = ch + cy;
            orr = sh / den; oii = sy / den;
        }
        S[xx * 16 + yy] = make_float2(orr, oii);
    }
    __syncthreads();
    for (int o = tid; o < 64 * m; o += 256) {
        int e = o / m, xx = o - e * m;
        float re = 0.f, im = 0.f;
        for (int yy = 0; yy < m; yy++) {
            float2 sv = S[xx * 16 + yy], kv = kf[e * 16 + yy];
            re += sv.x * kv.x - sv.y * kv.y;
            im += sv.x * kv.y + sv.y * kv.x;
        }
        OF[(long)bh * 1024 + e * 16 + xx] = make_float2(re, im);
    }
}

// ---------------------------------------------------------------------------
// irfft
// ---------------------------------------------------------------------------
__global__ __launch_bounds__(256) void irfft_kernel(
    const float2* __restrict__ OF, float* __restrict__ out,
    const float* __restrict__ addsrc, int L, int m)
{
    __shared__ float twc[512], tws[512];
    __shared__ float2 of_s[64][16];
    int tid = threadIdx.x, ec = blockIdx.x, b = blockIdx.y;

    for (int i = tid; i < L; i += 256) {
        float th = 6.2831853071795864f * (float)i / (float)L;
        float s, c; sincosf(th, &s, &c);
        twc[i] = c; tws[i] = s;
    }
    float inv = 1.f / ((float)L * 4096.f);
    for (int i = tid; i < 1024; i += 256) {
        int el = i >> 4, xx = i & 15;
        int e = ec * 8 + (el >> 3), h = el & 7;
        float2 v = (xx < m) ? OF[((long)((b * 8 + h) * 64 + e)) * 16 + xx]
                            : make_float2(0.f, 0.f);
        float w = (xx == 0) ? inv : 2.f * inv;
        of_s[el][xx] = make_float2(v.x * w, v.y * w);
    }
    __syncthreads();

    for (long i = tid; i < (long)L * 64; i += 256) {
        int el = (int)(i & 63);
        int t = (int)(i >> 6);
        float acc = 0.f;
#pragma unroll
        for (int xx = 0; xx < 16; xx++) {
            int id = (xx * t) & (L - 1);
            float2 f = of_s[el][xx];
            acc += f.x * twc[id] - f.y * tws[id];
        }
        long dst = ((long)(b * L + t)) * CKD + ec * 64 + el;
        out[dst] = acc + (addsrc ? addsrc[dst] : 0.f);
    }
}

__global__ void zero_kernel(float* p, long n) {
    long i = (long)blockIdx.x * blockDim.x + threadIdx.x;
    if (i < n) p[i] = 0.f;
}

// ---------------------------------------------------------------------------
extern "C" void kernel_launch(void* const* d_in, const int* in_sizes, int n_in,
                              void* d_out, int out_size)
{
    const float* q    = (const float*)d_in[0];
    const float* k    = (const float*)d_in[1];
    const float* Lq_w = (const float*)d_in[3];
    const float* Lq_b = (const float*)d_in[4];
    const float* Lk_w = (const float*)d_in[5];
    const float* Lk_b = (const float*)d_in[6];
    const float* out_w = (const float*)d_in[9];
    const float* out_b = (const float*)d_in[10];
    const float* ec_s = (const float*)d_in[11];
    const float* ec_d = (const float*)d_in[12];
    const float* rc_e = (const float*)d_in[13];
    const float* rc_o = (const float*)d_in[14];

    float *QA, *QB, *KA, *KB, *DQ, *DK, *US, *UD, *VA, *VB;
    float2 *QF, *KF, *OF;
    cudaGetSymbolAddress((void**)&QA, g_QA);
    cudaGetSymbolAddress((void**)&QB, g_QB);
    cudaGetSymbolAddress((void**)&KA, g_KA);
    cudaGetSymbolAddress((void**)&KB, g_KB);
    cudaGetSymbolAddress((void**)&DQ, g_DQ);
    cudaGetSymbolAddress((void**)&DK, g_DK);
    cudaGetSymbolAddress((void**)&US, g_US);
    cudaGetSymbolAddress((void**)&UD, g_UD);
    cudaGetSymbolAddress((void**)&VA, g_VA);
    cudaGetSymbolAddress((void**)&VB, g_VB);
    cudaGetSymbolAddress((void**)&QF, g_QF);
    cudaGetSymbolAddress((void**)&KF, g_KF);
    cudaGetSymbolAddress((void**)&OF, g_OF);

    dim3 gg(4, 128);
    gemm_tf32<<<gg, 256>>>(q, Lq_w, Lq_b, QA);
    gemm_tf32<<<gg, 256>>>(k, Lk_w, Lk_b, KA);

    float* qc = QA; float* qn = QB;
    float* kc = KA; float* kn = KB;
    long offs[10]; int Lhs[10];
    long off = 0;
    int L = 1024;
    for (int i = 0; i < 10; i++) {
        int Lh = L >> 1;
        Lhs[i] = Lh; offs[i] = off;
        off += (long)BB * Lh * CKD;
        int m = (Lh / 2 < 16) ? (Lh / 2) : 16;
        long total = (long)BB * Lh * 64;
        int blocks = (int)((total + 255) / 256);

        wavelet_kernel<<<blocks, 256>>>(qc, ec_d, ec_s, DQ, qn, Lh);
        wavelet_kernel<<<blocks, 256>>>(kc, ec_d, ec_s, DK, kn, Lh);

        long sz = (long)BB * Lh * CKD;
        if (m > 0) {
            dim3 fg(8, BB);
            rfft_kernel<<<fg, 256>>>(DQ, QF, Lh, m);
            rfft_kernel<<<fg, 256>>>(DK, KF, Lh, m);
            attn_kernel<<<128, 256>>>(QF, KF, OF, m);
            irfft_kernel<<<fg, 256>>>(OF, US + offs[i], nullptr, Lh, m);
            rfft_kernel<<<fg, 256>>>(qn, QF, Lh, m);
            rfft_kernel<<<fg, 256>>>(kn, KF, Lh, m);
            attn_kernel<<<128, 256>>>(QF, KF, OF, m);
            irfft_kernel<<<fg, 256>>>(OF, UD + offs[i], US + offs[i], Lh, m);
        } else {
            zero_kernel<<<(int)((sz + 255) / 256), 256>>>(US + offs[i], sz);
            zero_kernel<<<(int)((sz + 255) / 256), 256>>>(UD + offs[i], sz);
        }
        { float* t = qc; qc = qn; qn = t; }
        { float* t = kc; kc = kn; kn = t; }
        L = Lh;
    }

    zero_kernel<<<32, 256>>>(VA, (long)BB * 1 * CKD);
    float* vc = VA; float* vn = VB;
    for (int i = 9; i >= 0; i--) {
        int Lv = Lhs[i];
        long total = (long)BB * Lv * 64;
        recon_kernel<<<(int)((total + 255) / 256), 256>>>(
            vc, US + offs[i], UD + offs[i], rc_e, rc_o, vn, Lv);
        float* t = vc; vc = vn; vn = t;
    }

    gemm_tf32<<<gg, 256>>>(vc, out_w, out_b, (float*)d_out);
}

// round 7
// speedup vs baseline: 1.3355x; 1.3355x over previous
#include <cuda_runtime.h>
#include <cuda_bf16.h>
#include <math.h>
#include <cstdint>

// ---------------------------------------------------------------------------
// MultiWaveletCross on GB300 — round 5: bf16x3 mma.sync GEMMs
// (tcgen05 unavailable: harness PTX target is sm_103 without 'a' feature)
// ---------------------------------------------------------------------------

#define BB 16
#define CKD 512
#define NTOK 16384

__device__ float g_QA[8388608];
__device__ float g_QB[8388608];
__device__ float g_KA[8388608];
__device__ float g_KB[8388608];
__device__ float g_DQ[4194304];
__device__ float g_DK[4194304];
__device__ float g_US[8380416];
__device__ float g_UD[8380416];
__device__ float g_VA[8388608];
__device__ float g_VB[8388608];
__device__ float2 g_QF[131072];
__device__ float2 g_KF[131072];
__device__ float2 g_OF[131072];
// bf16 split scratch
__device__ __nv_bfloat16 g_Ah[8388608];
__device__ __nv_bfloat16 g_Al[8388608];
__device__ __nv_bfloat16 g_WhT[262144];
__device__ __nv_bfloat16 g_WlT[262144];

__device__ __forceinline__ uint32_t smem_to_u32(const void* p) {
    uint32_t a;
    asm("{ .reg .u64 t; cvta.to.shared.u64 t, %1; cvt.u32.u64 %0, t; }"
        : "=r"(a) : "l"(p));
    return a;
}

// ---------------------------------------------------------------------------
// split kernels: fp32 -> bf16 hi + bf16 lo
// ---------------------------------------------------------------------------
__global__ __launch_bounds__(256) void split_a_kernel(
    const float* __restrict__ x, __nv_bfloat16* __restrict__ h,
    __nv_bfloat16* __restrict__ l, long n4)
{
    long i = (long)blockIdx.x * 256 + threadIdx.x;
    if (i >= n4) return;
    float4 v = *(const float4*)(x + i * 4);
    __nv_bfloat16 h0 = __float2bfloat16(v.x);
    __nv_bfloat16 h1 = __float2bfloat16(v.y);
    __nv_bfloat16 h2 = __float2bfloat16(v.z);
    __nv_bfloat16 h3 = __float2bfloat16(v.w);
    __nv_bfloat16 l0 = __float2bfloat16(v.x - __bfloat162float(h0));
    __nv_bfloat16 l1 = __float2bfloat16(v.y - __bfloat162float(h1));
    __nv_bfloat16 l2 = __float2bfloat16(v.z - __bfloat162float(h2));
    __nv_bfloat16 l3 = __float2bfloat16(v.w - __bfloat162float(h3));
    __nv_bfloat162* hp = (__nv_bfloat162*)(h + i * 4);
    __nv_bfloat162* lp = (__nv_bfloat162*)(l + i * 4);
    hp[0] = __nv_bfloat162(h0, h1); hp[1] = __nv_bfloat162(h2, h3);
    lp[0] = __nv_bfloat162(l0, l1); lp[1] = __nv_bfloat162(l2, l3);
}

// W [512(k)][512(n)] -> WhT/WlT [512(n)][512(k)]
__global__ __launch_bounds__(256) void split_wt_kernel(
    const float* __restrict__ W, __nv_bfloat16* __restrict__ hT,
    __nv_bfloat16* __restrict__ lT)
{
    __shared__ float t[32][33];
    int tx = threadIdx.x, ty = threadIdx.y;
    int bx = blockIdx.x, by = blockIdx.y;
#pragma unroll
    for (int j = 0; j < 4; j++)
        t[ty + 8 * j][tx] = W[(size_t)(by * 32 + ty + 8 * j) * 512 + bx * 32 + tx];
    __syncthreads();
#pragma unroll
    for (int j = 0; j < 4; j++) {
        float v = t[tx][ty + 8 * j];
        int n_o = bx * 32 + ty + 8 * j;
        int k_o = by * 32 + tx;
        __nv_bfloat16 hb = __float2bfloat16(v);
        __nv_bfloat16 lb = __float2bfloat16(v - __bfloat162float(hb));
        hT[(size_t)n_o * 512 + k_o] = hb;
        lT[(size_t)n_o * 512 + k_o] = lb;
    }
}

// ---------------------------------------------------------------------------
// bf16x3 GEMM: C[M,512] = (Ah+Al)[M,512] @ (Bh+Bl)^T[512,512] + bias
// A [m][k] bf16, B [n][k] bf16. CTA 128x128, 8 warps 2x4, warp 64x32, KB=32.
// cp.async double-buffered, ldmatrix fragments, products hh + hl + lh.
// ---------------------------------------------------------------------------
#define LDAE 40                  // bf16 elems per smem row (32 + 8 pad)
#define ARR_B (128 * LDAE * 2)   // 10240 bytes per array
#define BUF_B (4 * ARR_B)        // 40960 bytes per buffer
#define GSMEM_BYTES (2 * BUF_B)  // 81920

#define CP_ASYNC16(dst, src) \
    asm volatile("cp.async.cg.shared.global [%0], [%1], 16;" \
        :: "r"(dst), "l"(src))
#define CP_COMMIT() asm volatile("cp.async.commit_group;" ::: "memory")
#define CP_WAIT1() asm volatile("cp.async.wait_group 1;" ::: "memory")
#define CP_WAIT0() asm volatile("cp.async.wait_group 0;" ::: "memory")

#define LDSM_X4(R, addr) \
    asm volatile("ldmatrix.sync.aligned.m8n8.x4.shared.b16 {%0,%1,%2,%3}, [%4];" \
        : "=r"((R)[0]), "=r"((R)[1]), "=r"((R)[2]), "=r"((R)[3]) : "r"(addr))
#define LDSM_X2(R, addr) \
    asm volatile("ldmatrix.sync.aligned.m8n8.x2.shared.b16 {%0,%1}, [%2];" \
        : "=r"((R)[0]), "=r"((R)[1]) : "r"(addr))

#define MMA_BF16(ACC, A, B0, B1) \
    asm volatile( \
        "mma.sync.aligned.m16n8k16.row.col.f32.bf16.bf16.f32 " \
        "{%0,%1,%2,%3}, {%4,%5,%6,%7}, {%8,%9}, {%0,%1,%2,%3};" \
        : "+f"((ACC)[0]), "+f"((ACC)[1]), "+f"((ACC)[2]), "+f"((ACC)[3]) \
        : "r"((A)[0]), "r"((A)[1]), "r"((A)[2]), "r"((A)[3]), \
          "r"(B0), "r"(B1))

__global__ __launch_bounds__(256) void gemm_bf16x3(
    const __nv_bfloat16* __restrict__ Ah, const __nv_bfloat16* __restrict__ Al,
    const __nv_bfloat16* __restrict__ Bh, const __nv_bfloat16* __restrict__ Bl,
    const float* __restrict__ bias, float* __restrict__ C)
{
    extern __shared__ __align__(16) char dsm[];
    const int tid = threadIdx.x;
    const int wid = tid >> 5, lane = tid & 31;
    const int bm = blockIdx.y * 128, bn = blockIdx.x * 128;
    const int wm = (wid >> 2) * 64, wn = (wid & 3) * 32;
    const int lr = lane >> 2, lc = lane & 3;
    const uint32_t sb = smem_to_u32(dsm);

    float acc[4][4][4];
#pragma unroll
    for (int mi = 0; mi < 4; mi++)
#pragma unroll
        for (int ni = 0; ni < 4; ni++)
#pragma unroll
            for (int r = 0; r < 4; r++) acc[mi][ni][r] = 0.f;

    const __nv_bfloat16* gsrc0 = Ah + (size_t)bm * 512;
    const __nv_bfloat16* gsrc1 = Al + (size_t)bm * 512;
    const __nv_bfloat16* gsrc2 = Bh + (size_t)bn * 512;
    const __nv_bfloat16* gsrc3 = Bl + (size_t)bn * 512;

    // producer: per kblock, 4 arrays x 128 rows x 4 x 16B chunks = 8/thread
    const int pc0 = tid, pc1 = tid + 256;        // chunk ids within array
    const int pr0 = pc0 >> 2, po0 = (pc0 & 3);
    const int pr1 = pc1 >> 2, po1 = (pc1 & 3);

#define PRODUCE(KB, BUF) do {                                                  \
    uint32_t base = sb + (BUF) * BUF_B;                                        \
    int kg = (KB) * 32;                                                        \
    CP_ASYNC16(base + pr0 * 80 + po0 * 16,                                     \
               gsrc0 + (size_t)pr0 * 512 + kg + po0 * 8);                      \
    CP_ASYNC16(base + pr1 * 80 + po1 * 16,                                     \
               gsrc0 + (size_t)pr1 * 512 + kg + po1 * 8);                      \
    CP_ASYNC16(base + ARR_B + pr0 * 80 + po0 * 16,                             \
               gsrc1 + (size_t)pr0 * 512 + kg + po0 * 8);                      \
    CP_ASYNC16(base + ARR_B + pr1 * 80 + po1 * 16,                             \
               gsrc1 + (size_t)pr1 * 512 + kg + po1 * 8);                      \
    CP_ASYNC16(base + 2 * ARR_B + pr0 * 80 + po0 * 16,                         \
               gsrc2 + (size_t)pr0 * 512 + kg + po0 * 8);                      \
    CP_ASYNC16(base + 2 * ARR_B + pr1 * 80 + po1 * 16,                         \
               gsrc2 + (size_t)pr1 * 512 + kg + po1 * 8);                      \
    CP_ASYNC16(base + 3 * ARR_B + pr0 * 80 + po0 * 16,                         \
               gsrc3 + (size_t)pr0 * 512 + kg + po0 * 8);                      \
    CP_ASYNC16(base + 3 * ARR_B + pr1 * 80 + po1 * 16,                         \
               gsrc3 + (size_t)pr1 * 512 + kg + po1 * 8);                      \
    CP_COMMIT();                                                               \
} while (0)

    // ldmatrix lane geometry
    const int a_row_off = (lane & 7) + ((lane >> 3) & 1) * 8;
    const int a_k_off = (lane >> 4) * 8;
    const int b_row_off = lane & 7;
    const int b_k_off = ((lane >> 3) & 1) * 8;

    PRODUCE(0, 0);
    for (int kb = 0; kb < 16; kb++) {
        if (kb < 15) PRODUCE(kb + 1, (kb + 1) & 1);
        if (kb < 15) { CP_WAIT1(); } else { CP_WAIT0(); }
        __syncthreads();
        const uint32_t base = sb + (kb & 1) * BUF_B;

#pragma unroll
        for (int k16 = 0; k16 < 32; k16 += 16) {
            uint32_t ah[4][4], al[4][4], bh[4][2], bl[4][2];
#pragma unroll
            for (int mi = 0; mi < 4; mi++) {
                uint32_t addr = base +
                    ((wm + mi * 16 + a_row_off) * LDAE + k16 + a_k_off) * 2;
                LDSM_X4(ah[mi], addr);
                LDSM_X4(al[mi], addr + ARR_B);
            }
#pragma unroll
            for (int ni = 0; ni < 4; ni++) {
                uint32_t addr = base + 2 * ARR_B +
                    ((wn + ni * 8 + b_row_off) * LDAE + k16 + b_k_off) * 2;
                LDSM_X2(bh[ni], addr);
                LDSM_X2(bl[ni], addr + ARR_B);
            }
#pragma unroll
            for (int mi = 0; mi < 4; mi++)
#pragma unroll
                for (int ni = 0; ni < 4; ni++) {
                    MMA_BF16(acc[mi][ni], ah[mi], bh[ni][0], bh[ni][1]);
                    MMA_BF16(acc[mi][ni], ah[mi], bl[ni][0], bl[ni][1]);
                    MMA_BF16(acc[mi][ni], al[mi], bh[ni][0], bh[ni][1]);
                }
        }
        __syncthreads();
    }

#pragma unroll
    for (int mi = 0; mi < 4; mi++) {
#pragma unroll
        for (int ni = 0; ni < 4; ni++) {
            int col = bn + wn + ni * 8 + 2 * lc;
            float2 bv = *(const float2*)(bias + col);
            int r0 = bm + wm + mi * 16 + lr;
            float2 o0 = make_float2(acc[mi][ni][0] + bv.x, acc[mi][ni][1] + bv.y);
            float2 o1 = make_float2(acc[mi][ni][2] + bv.x, acc[mi][ni][3] + bv.y);
            *(float2*)(C + (size_t)r0 * 512 + col) = o0;
            *(float2*)(C + (size_t)(r0 + 8) * 512 + col) = o1;
        }
    }
}

// ---------------------------------------------------------------------------
// Wavelet step
// ---------------------------------------------------------------------------
__global__ __launch_bounds__(256) void wavelet_kernel(
    const float* __restrict__ x, const float* __restrict__ ecd,
    const float* __restrict__ ecs, float* __restrict__ od,
    float* __restrict__ os, int Lh)
{
    __shared__ float wd[16][8], ws_[16][8];
    int tid = threadIdx.x;
    if (tid < 128)       wd[tid >> 3][tid & 7] = ecd[tid];
    else if (tid < 256)  { int t = tid - 128; ws_[t >> 3][t & 7] = ecs[t]; }
    __syncthreads();

    long idx = (long)blockIdx.x * 256 + tid;
    long total = (long)BB * Lh * 64;
    if (idx >= total) return;
    int c = (int)(idx & 63);
    long bt = idx >> 6;
    int t2 = (int)(bt % Lh);
    int b = (int)(bt / Lh);

    const float* p0 = x + ((long)(b * 2 * Lh + 2 * t2)) * CKD + c * 8;
    float a[16];
    *(float4*)(a)      = *(const float4*)(p0);
    *(float4*)(a + 4)  = *(const float4*)(p0 + 4);
    *(float4*)(a + 8)  = *(const float4*)(p0 + CKD);
    *(float4*)(a + 12) = *(const float4*)(p0 + CKD + 4);

    float rd[8], rs[8];
#pragma unroll
    for (int kk = 0; kk < 8; kk++) { rd[kk] = 0.f; rs[kk] = 0.f; }
#pragma unroll
    for (int j = 0; j < 16; j++)
#pragma unroll
        for (int kk = 0; kk < 8; kk++) {
            rd[kk] += a[j] * wd[j][kk];
            rs[kk] += a[j] * ws_[j][kk];
        }
    float* pd = od + ((long)(b * Lh + t2)) * CKD + c * 8;
    float* ps = os + ((long)(b * Lh + t2)) * CKD + c * 8;
    *(float4*)(pd)     = *(float4*)(rd);
    *(float4*)(pd + 4) = *(float4*)(rd + 4);
    *(float4*)(ps)     = *(float4*)(rs);
    *(float4*)(ps + 4) = *(float4*)(rs + 4);
}

// ---------------------------------------------------------------------------
// Reconstruction step
// ---------------------------------------------------------------------------
__global__ __launch_bounds__(256) void recon_kernel(
    const float* __restrict__ vin, const float* __restrict__ us,
    const float* __restrict__ ud, const float* __restrict__ rce,
    const float* __restrict__ rco, float* __restrict__ vout, int Lv)
{
    __shared__ float we[16][8], wo[16][8];
    int tid = threadIdx.x;
    if (tid < 128)       we[tid >> 3][tid & 7] = rce[tid];
    else if (tid < 256)  { int t = tid - 128; wo[t >> 3][t & 7] = rco[t]; }
    __syncthreads();

    long idx = (long)blockIdx.x * 256 + tid;
    long total = (long)BB * Lv * 64;
    if (idx >= total) return;
    int c = (int)(idx & 63);
    long bt = idx >> 6;
    int t = (int)(bt % Lv);
    int b = (int)(bt / Lv);

    long base = ((long)(b * Lv + t)) * CKD + c * 8;
    float a[16];
#pragma unroll
    for (int j = 0; j < 8; j++) a[j] = vin[base + j] + us[base + j];
    *(float4*)(a + 8)  = *(const float4*)(ud + base);
    *(float4*)(a + 12) = *(const float4*)(ud + base + 4);

    float re[8], ro[8];
#pragma unroll
    for (int kk = 0; kk < 8; kk++) { re[kk] = 0.f; ro[kk] = 0.f; }
#pragma unroll
    for (int j = 0; j < 16; j++)
#pragma unroll
        for (int kk = 0; kk < 8; kk++) {
            re[kk] += a[j] * we[j][kk];
            ro[kk] += a[j] * wo[j][kk];
        }
    float* pe = vout + ((long)(b * 2 * Lv + 2 * t)) * CKD + c * 8;
    *(float4*)(pe)           = *(float4*)(re);
    *(float4*)(pe + 4)       = *(float4*)(re + 4);
    *(float4*)(pe + CKD)     = *(float4*)(ro);
    *(float4*)(pe + CKD + 4) = *(float4*)(ro + 4);
}

// ---------------------------------------------------------------------------
// rfft (first m modes)
// ---------------------------------------------------------------------------
__global__ __launch_bounds__(256) void rfft_kernel(
    const float* __restrict__ x, float2* __restrict__ F, int L, int m)
{
    __shared__ float twc[512], tws[512];
    __shared__ float tile[64][64];
    int tid = threadIdx.x;
    int ec = blockIdx.x;
    int b = blockIdx.y;

    for (int i = tid; i < L; i += 256) {
        float th = 6.2831853071795864f * (float)i / (float)L;
        float s, c; sincosf(th, &s, &c);
        twc[i] = c; tws[i] = s;
    }

    int eh = tid >> 2;
    int xg = tid & 3;
    float ar[4] = {0.f, 0.f, 0.f, 0.f}, ai[4] = {0.f, 0.f, 0.f, 0.f};

    for (int t0 = 0; t0 < L; t0 += 64) {
        int tc = L - t0 < 64 ? L - t0 : 64;
        __syncthreads();
        for (int i = tid; i < tc * 64; i += 256) {
            int tt = i >> 6, el = i & 63;
            tile[tt][el] = x[((long)(b * L + t0 + tt)) * CKD + ec * 64 + el];
        }
        __syncthreads();
        for (int tt = 0; tt < tc; tt++) {
            float v = tile[tt][eh];
            int t = t0 + tt;
#pragma unroll
            for (int j = 0; j < 4; j++) {
                int xx = xg + j * 4;
                int id = (xx * t) & (L - 1);
                ar[j] += v * twc[id];
                ai[j] -= v * tws[id];
            }
        }
    }
    int e = ec * 8 + (eh >> 3), h = eh & 7;
    float2* dst = F + ((long)((b * 8 + h) * 64 + e)) * 16;
#pragma unroll
    for (int j = 0; j < 4; j++) {
        int xx = xg + j * 4;
        if (xx < m) dst[xx] = make_float2(ar[j], ai[j]);
    }
}

// ---------------------------------------------------------------------------
// attn
// ---------------------------------------------------------------------------
__global__ __launch_bounds__(256) void attn_kernel(
    const float2* __restrict__ QF, const float2* __restrict__ KF,
    float2* __restrict__ OF, int m)
{
    __shared__ float2 qf[1024], kf[1024], S[256];
    int bh = blockIdx.x, tid = threadIdx.x;
    const float2* qsrc = QF + (long)bh * 1024;
    const float2* ksrc = KF + (long)bh * 1024;
    for (int i = tid; i < 1024; i += 256) { qf[i] = qsrc[i]; kf[i] = ksrc[i]; }
    __syncthreads();

    for (int s = tid; s < m * m; s += 256) {
        int xx = s / m, yy = s - xx * m;
        float re = 0.f, im = 0.f;
#pragma unroll 8
        for (int e = 0; e < 64; e++) {
            float2 qv = qf[e * 16 + xx], kv = kf[e * 16 + yy];
            re += qv.x * kv.x - qv.y * kv.y;
            im += qv.x * kv.y + qv.y * kv.x;
        }
        float X = 2.f * re, Y = 2.f * im, orr, oii;
        if (fabsf(X) > 20.f) {
            orr = copysignf(1.f, X); oii = 0.f;
        } else {
            float ex = expf(X), enx = 1.f / ex;
            float sh = 0.5f * (ex - enx), ch = 0.5f * (ex + enx);
            float sy, cy; sincosf(Y, &sy, &cy);
            float den = ch + cy;
            orr = sh / den; oii = sy / den;
        }
        S[xx * 16 + yy] = make_float2(orr, oii);
    }
    __syncthreads();
    for (int o = tid; o < 64 * m; o += 256) {
        int e = o / m, xx = o - e * m;
        float re = 0.f, im = 0.f;
        for (int yy = 0; yy < m; yy++) {
            float2 sv = S[xx * 16 + yy], kv = kf[e * 16 + yy];
            re += sv.x * kv.x - sv.y * kv.y;
            im += sv.x * kv.y + sv.y * kv.x;
        }
        OF[(long)bh * 1024 + e * 16 + xx] = make_float2(re, im);
    }
}

// ---------------------------------------------------------------------------
// irfft
// ---------------------------------------------------------------------------
__global__ __launch_bounds__(256) void irfft_kernel(
    const float2* __restrict__ OF, float* __restrict__ out,
    const float* __restrict__ addsrc, int L, int m)
{
    __shared__ float twc[512], tws[512];
    __shared__ float2 of_s[64][16];
    int tid = threadIdx.x, ec = blockIdx.x, b = blockIdx.y;

    for (int i = tid; i < L; i += 256) {
        float th = 6.2831853071795864f * (float)i / (float)L;
        float s, c; sincosf(th, &s, &c);
        twc[i] = c; tws[i] = s;
    }
    float inv = 1.f / ((float)L * 4096.f);
    for (int i = tid; i < 1024; i += 256) {
        int el = i >> 4, xx = i & 15;
        int e = ec * 8 + (el >> 3), h = el & 7;
        float2 v = (xx < m) ? OF[((long)((b * 8 + h) * 64 + e)) * 16 + xx]
                            : make_float2(0.f, 0.f);
        float w = (xx == 0) ? inv : 2.f * inv;
        of_s[el][xx] = make_float2(v.x * w, v.y * w);
    }
    __syncthreads();

    for (long i = tid; i < (long)L * 64; i += 256) {
        int el = (int)(i & 63);
        int t = (int)(i >> 6);
        float acc = 0.f;
#pragma unroll
        for (int xx = 0; xx < 16; xx++) {
            int id = (xx * t) & (L - 1);
            float2 f = of_s[el][xx];
            acc += f.x * twc[id] - f.y * tws[id];
        }
        long dst = ((long)(b * L + t)) * CKD + ec * 64 + el;
        out[dst] = acc + (addsrc ? addsrc[dst] : 0.f);
    }
}

__global__ void zero_kernel(float* p, long n) {
    long i = (long)blockIdx.x * blockDim.x + threadIdx.x;
    if (i < n) p[i] = 0.f;
}

// ---------------------------------------------------------------------------
extern "C" void kernel_launch(void* const* d_in, const int* in_sizes, int n_in,
                              void* d_out, int out_size)
{
    const float* q    = (const float*)d_in[0];
    const float* k    = (const float*)d_in[1];
    const float* Lq_w = (const float*)d_in[3];
    const float* Lq_b = (const float*)d_in[4];
    const float* Lk_w = (const float*)d_in[5];
    const float* Lk_b = (const float*)d_in[6];
    const float* out_w = (const float*)d_in[9];
    const float* out_b = (const float*)d_in[10];
    const float* ec_s = (const float*)d_in[11];
    const float* ec_d = (const float*)d_in[12];
    const float* rc_e = (const float*)d_in[13];
    const float* rc_o = (const float*)d_in[14];

    float *QA, *QB, *KA, *KB, *DQ, *DK, *US, *UD, *VA, *VB;
    float2 *QF, *KF, *OF;
    __nv_bfloat16 *Ah, *Al, *WhT, *WlT;
    cudaGetSymbolAddress((void**)&QA, g_QA);
    cudaGetSymbolAddress((void**)&QB, g_QB);
    cudaGetSymbolAddress((void**)&KA, g_KA);
    cudaGetSymbolAddress((void**)&KB, g_KB);
    cudaGetSymbolAddress((void**)&DQ, g_DQ);
    cudaGetSymbolAddress((void**)&DK, g_DK);
    cudaGetSymbolAddress((void**)&US, g_US);
    cudaGetSymbolAddress((void**)&UD, g_UD);
    cudaGetSymbolAddress((void**)&VA, g_VA);
    cudaGetSymbolAddress((void**)&VB, g_VB);
    cudaGetSymbolAddress((void**)&QF, g_QF);
    cudaGetSymbolAddress((void**)&KF, g_KF);
    cudaGetSymbolAddress((void**)&OF, g_OF);
    cudaGetSymbolAddress((void**)&Ah, g_Ah);
    cudaGetSymbolAddress((void**)&Al, g_Al);
    cudaGetSymbolAddress((void**)&WhT, g_WhT);
    cudaGetSymbolAddress((void**)&WlT, g_WlT);

    cudaFuncSetAttribute(gemm_bf16x3,
                         cudaFuncAttributeMaxDynamicSharedMemorySize,
                         GSMEM_BYTES);

    dim3 gg(4, 128);
    dim3 tb(32, 8), tg(16, 16);

    // Q projection
    split_wt_kernel<<<tg, tb>>>(Lq_w, WhT, WlT);
    split_a_kernel<<<8192, 256>>>(q, Ah, Al, 2097152);
    gemm_bf16x3<<<gg, 256, GSMEM_BYTES>>>(Ah, Al, WhT, WlT, Lq_b, QA);
    // K projection
    split_wt_kernel<<<tg, tb>>>(Lk_w, WhT, WlT);
    split_a_kernel<<<8192, 256>>>(k, Ah, Al, 2097152);
    gemm_bf16x3<<<gg, 256, GSMEM_BYTES>>>(Ah, Al, WhT, WlT, Lk_b, KA);

    float* qc = QA; float* qn = QB;
    float* kc = KA; float* kn = KB;
    long offs[10]; int Lhs[10];
    long off = 0;
    int L = 1024;
    for (int i = 0; i < 10; i++) {
        int Lh = L >> 1;
        Lhs[i] = Lh; offs[i] = off;
        off += (long)BB * Lh * CKD;
        int m = (Lh / 2 < 16) ? (Lh / 2) : 16;
        long total = (long)BB * Lh * 64;
        int blocks = (int)((total + 255) / 256);

        wavelet_kernel<<<blocks, 256>>>(qc, ec_d, ec_s, DQ, qn, Lh);
        wavelet_kernel<<<blocks, 256>>>(kc, ec_d, ec_s, DK, kn, Lh);

        long sz = (long)BB * Lh * CKD;
        if (m > 0) {
            dim3 fg(8, BB);
            rfft_kernel<<<fg, 256>>>(DQ, QF, Lh, m);
            rfft_kernel<<<fg, 256>>>(DK, KF, Lh, m);
            attn_kernel<<<128, 256>>>(QF, KF, OF, m);
            irfft_kernel<<<fg, 256>>>(OF, US + offs[i], nullptr, Lh, m);
            rfft_kernel<<<fg, 256>>>(qn, QF, Lh, m);
            rfft_kernel<<<fg, 256>>>(kn, KF, Lh, m);
            attn_kernel<<<128, 256>>>(QF, KF, OF, m);
            irfft_kernel<<<fg, 256>>>(OF, UD + offs[i], US + offs[i], Lh, m);
        } else {
            zero_kernel<<<(int)((sz + 255) / 256), 256>>>(US + offs[i], sz);
            zero_kernel<<<(int)((sz + 255) / 256), 256>>>(UD + offs[i], sz);
        }
        { float* t = qc; qc = qn; qn = t; }
        { float* t = kc; kc = kn; kn = t; }
        L = Lh;
    }

    zero_kernel<<<32, 256>>>(VA, (long)BB * 1 * CKD);
    float* vc = VA; float* vn = VB;
    for (int i = 9; i >= 0; i--) {
        int Lv = Lhs[i];
        long total = (long)BB * Lv * 64;
        recon_kernel<<<(int)((total + 255) / 256), 256>>>(
            vc, US + offs[i], UD + offs[i], rc_e, rc_o, vn, Lv);
        float* t = vc; vc = vn; vn = t;
    }

    // Output projection
    split_wt_kernel<<<tg, tb>>>(out_w, WhT, WlT);
    split_a_kernel<<<8192, 256>>>(vc, Ah, Al, 2097152);
    gemm_bf16x3<<<gg, 256, GSMEM_BYTES>>>(Ah, Al, WhT, WlT, out_b, (float*)d_out);
}

// round 8
// speedup vs baseline: 1.8173x; 1.3607x over previous
#include <cuda_runtime.h>
#include <cuda_bf16.h>
#include <math.h>
#include <cstdint>

// ---------------------------------------------------------------------------
// MultiWaveletCross on GB300 — round 8: bf16x3 GEMMs + fused pyramid
// ---------------------------------------------------------------------------

#define BB 16
#define CKD 512
#define NTOK 16384

__device__ float g_QA[8388608];
__device__ float g_QB[8388608];
__device__ float g_KA[8388608];
__device__ float g_KB[8388608];
__device__ float g_DQ[4194304];
__device__ float g_DK[4194304];
__device__ float g_US[8380416];
__device__ float g_UD[8380416];
__device__ float g_VA[8388608];
__device__ float g_VB[8388608];
__device__ float2 g_QFs[131072];
__device__ float2 g_KFs[131072];
__device__ float2 g_QFd[131072];
__device__ float2 g_KFd[131072];
__device__ float2 g_OFs[131072];
__device__ float2 g_OFd[131072];
// bf16 split scratch
__device__ __nv_bfloat16 g_Ah[8388608];
__device__ __nv_bfloat16 g_Al[8388608];
__device__ __nv_bfloat16 g_Ah2[8388608];
__device__ __nv_bfloat16 g_Al2[8388608];
__device__ __nv_bfloat16 g_Wh0[262144];
__device__ __nv_bfloat16 g_Wl0[262144];
__device__ __nv_bfloat16 g_Wh1[262144];
__device__ __nv_bfloat16 g_Wl1[262144];
__device__ __nv_bfloat16 g_Wh2[262144];
__device__ __nv_bfloat16 g_Wl2[262144];

__device__ __forceinline__ uint32_t smem_to_u32(const void* p) {
    uint32_t a;
    asm("{ .reg .u64 t; cvta.to.shared.u64 t, %1; cvt.u32.u64 %0, t; }"
        : "=r"(a) : "l"(p));
    return a;
}

// ---------------------------------------------------------------------------
// split kernels
// ---------------------------------------------------------------------------
__device__ __forceinline__ void split_store4(
    __nv_bfloat16* h, __nv_bfloat16* l, long i, float4 v)
{
    __nv_bfloat16 h0 = __float2bfloat16(v.x);
    __nv_bfloat16 h1 = __float2bfloat16(v.y);
    __nv_bfloat16 h2 = __float2bfloat16(v.z);
    __nv_bfloat16 h3 = __float2bfloat16(v.w);
    __nv_bfloat16 l0 = __float2bfloat16(v.x - __bfloat162float(h0));
    __nv_bfloat16 l1 = __float2bfloat16(v.y - __bfloat162float(h1));
    __nv_bfloat16 l2 = __float2bfloat16(v.z - __bfloat162float(h2));
    __nv_bfloat16 l3 = __float2bfloat16(v.w - __bfloat162float(h3));
    __nv_bfloat162* hp = (__nv_bfloat162*)(h + i * 4);
    __nv_bfloat162* lp = (__nv_bfloat162*)(l + i * 4);
    hp[0] = __nv_bfloat162(h0, h1); hp[1] = __nv_bfloat162(h2, h3);
    lp[0] = __nv_bfloat162(l0, l1); lp[1] = __nv_bfloat162(l2, l3);
}

// two streams (q and k) in one launch, grid.y selects
__global__ __launch_bounds__(256) void split_a2_kernel(
    const float* __restrict__ x0, const float* __restrict__ x1,
    __nv_bfloat16* __restrict__ h0, __nv_bfloat16* __restrict__ l0,
    __nv_bfloat16* __restrict__ h1, __nv_bfloat16* __restrict__ l1,
    long n4)
{
    long i = (long)blockIdx.x * 256 + threadIdx.x;
    if (i >= n4) return;
    const float* x = blockIdx.y ? x1 : x0;
    __nv_bfloat16* h = blockIdx.y ? h1 : h0;
    __nv_bfloat16* l = blockIdx.y ? l1 : l0;
    split_store4(h, l, i, *(const float4*)(x + i * 4));
}

// three weights transposed+split in one launch, grid.z selects
__global__ __launch_bounds__(256) void split_wt3_kernel(
    const float* __restrict__ W0, const float* __restrict__ W1,
    const float* __restrict__ W2,
    __nv_bfloat16* __restrict__ h0, __nv_bfloat16* __restrict__ l0,
    __nv_bfloat16* __restrict__ h1, __nv_bfloat16* __restrict__ l1,
    __nv_bfloat16* __restrict__ h2, __nv_bfloat16* __restrict__ l2)
{
    __shared__ float t[32][33];
    int tx = threadIdx.x, ty = threadIdx.y;
    int bx = blockIdx.x, by = blockIdx.y, bz = blockIdx.z;
    const float* W = bz == 0 ? W0 : (bz == 1 ? W1 : W2);
    __nv_bfloat16* hT = bz == 0 ? h0 : (bz == 1 ? h1 : h2);
    __nv_bfloat16* lT = bz == 0 ? l0 : (bz == 1 ? l1 : l2);
#pragma unroll
    for (int j = 0; j < 4; j++)
        t[ty + 8 * j][tx] = W[(size_t)(by * 32 + ty + 8 * j) * 512 + bx * 32 + tx];
    __syncthreads();
#pragma unroll
    for (int j = 0; j < 4; j++) {
        float v = t[tx][ty + 8 * j];
        int n_o = bx * 32 + ty + 8 * j;
        int k_o = by * 32 + tx;
        __nv_bfloat16 hb = __float2bfloat16(v);
        __nv_bfloat16 lb = __float2bfloat16(v - __bfloat162float(hb));
        hT[(size_t)n_o * 512 + k_o] = hb;
        lT[(size_t)n_o * 512 + k_o] = lb;
    }
}

// ---------------------------------------------------------------------------
// bf16x3 GEMM core
// ---------------------------------------------------------------------------
#define LDAE 40
#define ARR_B (128 * LDAE * 2)
#define BUF_B (4 * ARR_B)
#define GSMEM_BYTES (2 * BUF_B)

#define CP_ASYNC16(dst, src) \
    asm volatile("cp.async.cg.shared.global [%0], [%1], 16;" \
        :: "r"(dst), "l"(src))
#define CP_COMMIT() asm volatile("cp.async.commit_group;" ::: "memory")
#define CP_WAIT1() asm volatile("cp.async.wait_group 1;" ::: "memory")
#define CP_WAIT0() asm volatile("cp.async.wait_group 0;" ::: "memory")

#define LDSM_X4(R, addr) \
    asm volatile("ldmatrix.sync.aligned.m8n8.x4.shared.b16 {%0,%1,%2,%3}, [%4];" \
        : "=r"((R)[0]), "=r"((R)[1]), "=r"((R)[2]), "=r"((R)[3]) : "r"(addr))
#define LDSM_X2(R, addr) \
    asm volatile("ldmatrix.sync.aligned.m8n8.x2.shared.b16 {%0,%1}, [%2];" \
        : "=r"((R)[0]), "=r"((R)[1]) : "r"(addr))

#define MMA_BF16(ACC, A, B0, B1) \
    asm volatile( \
        "mma.sync.aligned.m16n8k16.row.col.f32.bf16.bf16.f32 " \
        "{%0,%1,%2,%3}, {%4,%5,%6,%7}, {%8,%9}, {%0,%1,%2,%3};" \
        : "+f"((ACC)[0]), "+f"((ACC)[1]), "+f"((ACC)[2]), "+f"((ACC)[3]) \
        : "r"((A)[0]), "r"((A)[1]), "r"((A)[2]), "r"((A)[3]), \
          "r"(B0), "r"(B1))

__device__ __forceinline__ void gemm_core(
    char* dsm,
    const __nv_bfloat16* __restrict__ Ah, const __nv_bfloat16* __restrict__ Al,
    const __nv_bfloat16* __restrict__ Bh, const __nv_bfloat16* __restrict__ Bl,
    const float* __restrict__ bias, float* __restrict__ C)
{
    const int tid = threadIdx.x;
    const int wid = tid >> 5, lane = tid & 31;
    const int bm = blockIdx.y * 128, bn = blockIdx.x * 128;
    const int wm = (wid >> 2) * 64, wn = (wid & 3) * 32;
    const int lr = lane >> 2, lc = lane & 3;
    const uint32_t sb = smem_to_u32(dsm);

    float acc[4][4][4];
#pragma unroll
    for (int mi = 0; mi < 4; mi++)
#pragma unroll
        for (int ni = 0; ni < 4; ni++)
#pragma unroll
            for (int r = 0; r < 4; r++) acc[mi][ni][r] = 0.f;

    const __nv_bfloat16* gsrc0 = Ah + (size_t)bm * 512;
    const __nv_bfloat16* gsrc1 = Al + (size_t)bm * 512;
    const __nv_bfloat16* gsrc2 = Bh + (size_t)bn * 512;
    const __nv_bfloat16* gsrc3 = Bl + (size_t)bn * 512;

    const int pc0 = tid, pc1 = tid + 256;
    const int pr0 = pc0 >> 2, po0 = (pc0 & 3);
    const int pr1 = pc1 >> 2, po1 = (pc1 & 3);

#define PRODUCE(KB, BUF) do {                                                  \
    uint32_t base = sb + (BUF) * BUF_B;                                        \
    int kg = (KB) * 32;                                                        \
    CP_ASYNC16(base + pr0 * 80 + po0 * 16,                                     \
               gsrc0 + (size_t)pr0 * 512 + kg + po0 * 8);                      \
    CP_ASYNC16(base + pr1 * 80 + po1 * 16,                                     \
               gsrc0 + (size_t)pr1 * 512 + kg + po1 * 8);                      \
    CP_ASYNC16(base + ARR_B + pr0 * 80 + po0 * 16,                             \
               gsrc1 + (size_t)pr0 * 512 + kg + po0 * 8);                      \
    CP_ASYNC16(base + ARR_B + pr1 * 80 + po1 * 16,                             \
               gsrc1 + (size_t)pr1 * 512 + kg + po1 * 8);                      \
    CP_ASYNC16(base + 2 * ARR_B + pr0 * 80 + po0 * 16,                         \
               gsrc2 + (size_t)pr0 * 512 + kg + po0 * 8);                      \
    CP_ASYNC16(base + 2 * ARR_B + pr1 * 80 + po1 * 16,                         \
               gsrc2 + (size_t)pr1 * 512 + kg + po1 * 8);                      \
    CP_ASYNC16(base + 3 * ARR_B + pr0 * 80 + po0 * 16,                         \
               gsrc3 + (size_t)pr0 * 512 + kg + po0 * 8);                      \
    CP_ASYNC16(base + 3 * ARR_B + pr1 * 80 + po1 * 16,                         \
               gsrc3 + (size_t)pr1 * 512 + kg + po1 * 8);                      \
    CP_COMMIT();                                                               \
} while (0)

    const int a_row_off = (lane & 7) + ((lane >> 3) & 1) * 8;
    const int a_k_off = (lane >> 4) * 8;
    const int b_row_off = lane & 7;
    const int b_k_off = ((lane >> 3) & 1) * 8;

    PRODUCE(0, 0);
    for (int kb = 0; kb < 16; kb++) {
        if (kb < 15) PRODUCE(kb + 1, (kb + 1) & 1);
        if (kb < 15) { CP_WAIT1(); } else { CP_WAIT0(); }
        __syncthreads();
        const uint32_t base = sb + (kb & 1) * BUF_B;

#pragma unroll
        for (int k16 = 0; k16 < 32; k16 += 16) {
            uint32_t ah[4][4], al[4][4], bh[4][2], bl[4][2];
#pragma unroll
            for (int mi = 0; mi < 4; mi++) {
                uint32_t addr = base +
                    ((wm + mi * 16 + a_row_off) * LDAE + k16 + a_k_off) * 2;
                LDSM_X4(ah[mi], addr);
                LDSM_X4(al[mi], addr + ARR_B);
            }
#pragma unroll
            for (int ni = 0; ni < 4; ni++) {
                uint32_t addr = base + 2 * ARR_B +
                    ((wn + ni * 8 + b_row_off) * LDAE + k16 + b_k_off) * 2;
                LDSM_X2(bh[ni], addr);
                LDSM_X2(bl[ni], addr + ARR_B);
            }
#pragma unroll
            for (int mi = 0; mi < 4; mi++)
#pragma unroll
                for (int ni = 0; ni < 4; ni++) {
                    MMA_BF16(acc[mi][ni], ah[mi], bh[ni][0], bh[ni][1]);
                    MMA_BF16(acc[mi][ni], ah[mi], bl[ni][0], bl[ni][1]);
                    MMA_BF16(acc[mi][ni], al[mi], bh[ni][0], bh[ni][1]);
                }
        }
        __syncthreads();
    }

#pragma unroll
    for (int mi = 0; mi < 4; mi++) {
#pragma unroll
        for (int ni = 0; ni < 4; ni++) {
            int col = bn + wn + ni * 8 + 2 * lc;
            float2 bv = *(const float2*)(bias + col);
            int r0 = bm + wm + mi * 16 + lr;
            float2 o0 = make_float2(acc[mi][ni][0] + bv.x, acc[mi][ni][1] + bv.y);
            float2 o1 = make_float2(acc[mi][ni][2] + bv.x, acc[mi][ni][3] + bv.y);
            *(float2*)(C + (size_t)r0 * 512 + col) = o0;
            *(float2*)(C + (size_t)(r0 + 8) * 512 + col) = o1;
        }
    }
#undef PRODUCE
}

__global__ __launch_bounds__(256) void gemm_bf16x3(
    const __nv_bfloat16* __restrict__ Ah, const __nv_bfloat16* __restrict__ Al,
    const __nv_bfloat16* __restrict__ Bh, const __nv_bfloat16* __restrict__ Bl,
    const float* __restrict__ bias, float* __restrict__ C)
{
    extern __shared__ __align__(16) char dsm[];
    gemm_core(dsm, Ah, Al, Bh, Bl, bias, C);
}

// dual GEMM: grid.z picks problem 0 (q) or 1 (k)
__global__ __launch_bounds__(256) void gemm_bf16x3_dual(
    const __nv_bfloat16* __restrict__ Ah0, const __nv_bfloat16* __restrict__ Al0,
    const __nv_bfloat16* __restrict__ Bh0, const __nv_bfloat16* __restrict__ Bl0,
    const float* __restrict__ b0, float* __restrict__ C0,
    const __nv_bfloat16* __restrict__ Ah1, const __nv_bfloat16* __restrict__ Al1,
    const __nv_bfloat16* __restrict__ Bh1, const __nv_bfloat16* __restrict__ Bl1,
    const float* __restrict__ b1, float* __restrict__ C1)
{
    extern __shared__ __align__(16) char dsm[];
    if (blockIdx.z == 0)
        gemm_core(dsm, Ah0, Al0, Bh0, Bl0, b0, C0);
    else
        gemm_core(dsm, Ah1, Al1, Bh1, Bl1, b1, C1);
}

// ---------------------------------------------------------------------------
// Wavelet step — q and k in one launch (grid.y selects stream)
// ---------------------------------------------------------------------------
__global__ __launch_bounds__(256) void wavelet2_kernel(
    const float* __restrict__ xq, const float* __restrict__ xk,
    const float* __restrict__ ecd, const float* __restrict__ ecs,
    float* __restrict__ dq, float* __restrict__ qn,
    float* __restrict__ dk, float* __restrict__ kn, int Lh)
{
    __shared__ float wd[16][8], ws_[16][8];
    int tid = threadIdx.x;
    if (tid < 128)       wd[tid >> 3][tid & 7] = ecd[tid];
    else if (tid < 256)  { int t = tid - 128; ws_[t >> 3][t & 7] = ecs[t]; }
    __syncthreads();

    const float* x = blockIdx.y ? xk : xq;
    float* od = blockIdx.y ? dk : dq;
    float* os = blockIdx.y ? kn : qn;

    long idx = (long)blockIdx.x * 256 + tid;
    long total = (long)BB * Lh * 64;
    if (idx >= total) return;
    int c = (int)(idx & 63);
    long bt = idx >> 6;
    int t2 = (int)(bt % Lh);
    int b = (int)(bt / Lh);

    const float* p0 = x + ((long)(b * 2 * Lh + 2 * t2)) * CKD + c * 8;
    float a[16];
    *(float4*)(a)      = *(const float4*)(p0);
    *(float4*)(a + 4)  = *(const float4*)(p0 + 4);
    *(float4*)(a + 8)  = *(const float4*)(p0 + CKD);
    *(float4*)(a + 12) = *(const float4*)(p0 + CKD + 4);

    float rd[8], rs[8];
#pragma unroll
    for (int kk = 0; kk < 8; kk++) { rd[kk] = 0.f; rs[kk] = 0.f; }
#pragma unroll
    for (int j = 0; j < 16; j++)
#pragma unroll
        for (int kk = 0; kk < 8; kk++) {
            rd[kk] += a[j] * wd[j][kk];
            rs[kk] += a[j] * ws_[j][kk];
        }
    float* pd = od + ((long)(b * Lh + t2)) * CKD + c * 8;
    float* ps = os + ((long)(b * Lh + t2)) * CKD + c * 8;
    *(float4*)(pd)     = *(float4*)(rd);
    *(float4*)(pd + 4) = *(float4*)(rd + 4);
    *(float4*)(ps)     = *(float4*)(rs);
    *(float4*)(ps + 4) = *(float4*)(rs + 4);
}

// ---------------------------------------------------------------------------
// Reconstruction step (optionally emits bf16 hi/lo split of the output)
// ---------------------------------------------------------------------------
__global__ __launch_bounds__(256) void recon_kernel(
    const float* __restrict__ vin, const float* __restrict__ us,
    const float* __restrict__ ud, const float* __restrict__ rce,
    const float* __restrict__ rco, float* __restrict__ vout, int Lv,
    __nv_bfloat16* __restrict__ oh, __nv_bfloat16* __restrict__ ol,
    int do_split)
{
    __shared__ float we[16][8], wo[16][8];
    int tid = threadIdx.x;
    if (tid < 128)       we[tid >> 3][tid & 7] = rce[tid];
    else if (tid < 256)  { int t = tid - 128; wo[t >> 3][t & 7] = rco[t]; }
    __syncthreads();

    long idx = (long)blockIdx.x * 256 + tid;
    long total = (long)BB * Lv * 64;
    if (idx >= total) return;
    int c = (int)(idx & 63);
    long bt = idx >> 6;
    int t = (int)(bt % Lv);
    int b = (int)(bt / Lv);

    long base = ((long)(b * Lv + t)) * CKD + c * 8;
    float a[16];
#pragma unroll
    for (int j = 0; j < 8; j++) a[j] = vin[base + j] + us[base + j];
    *(float4*)(a + 8)  = *(const float4*)(ud + base);
    *(float4*)(a + 12) = *(const float4*)(ud + base + 4);

    float re[8], ro[8];
#pragma unroll
    for (int kk = 0; kk < 8; kk++) { re[kk] = 0.f; ro[kk] = 0.f; }
#pragma unroll
    for (int j = 0; j < 16; j++)
#pragma unroll
        for (int kk = 0; kk < 8; kk++) {
            re[kk] += a[j] * we[j][kk];
            ro[kk] += a[j] * wo[j][kk];
        }
    long obase = ((long)(b * 2 * Lv + 2 * t)) * CKD + c * 8;
    float* pe = vout + obase;
    *(float4*)(pe)           = *(float4*)(re);
    *(float4*)(pe + 4)       = *(float4*)(re + 4);
    *(float4*)(pe + CKD)     = *(float4*)(ro);
    *(float4*)(pe + CKD + 4) = *(float4*)(ro + 4);

    if (do_split) {
        split_store4(oh, ol, (obase >> 2),           *(float4*)(re));
        split_store4(oh, ol, (obase >> 2) + 1,       *(float4*)(re + 4));
        split_store4(oh, ol, ((obase + CKD) >> 2),     *(float4*)(ro));
        split_store4(oh, ol, ((obase + CKD) >> 2) + 1, *(float4*)(ro + 4));
    }
}

// ---------------------------------------------------------------------------
// rfft x4 streams in one launch: grid (8, B, 4)
// ---------------------------------------------------------------------------
__global__ __launch_bounds__(256) void rfft4_kernel(
    const float* __restrict__ s0, const float* __restrict__ s1,
    const float* __restrict__ s2, const float* __restrict__ s3,
    float2* __restrict__ F0, float2* __restrict__ F1,
    float2* __restrict__ F2, float2* __restrict__ F3,
    int L, int m)
{
    __shared__ float twc[512], tws[512];
    __shared__ float tile[64][64];
    int tid = threadIdx.x;
    int ec = blockIdx.x;
    int b = blockIdx.y;
    int z = blockIdx.z;
    const float* x = z == 0 ? s0 : (z == 1 ? s1 : (z == 2 ? s2 : s3));
    float2* F = z == 0 ? F0 : (z == 1 ? F1 : (z == 2 ? F2 : F3));

    for (int i = tid; i < L; i += 256) {
        float th = 6.2831853071795864f * (float)i / (float)L;
        float s, c; sincosf(th, &s, &c);
        twc[i] = c; tws[i] = s;
    }

    int eh = tid >> 2;
    int xg = tid & 3;
    float ar[4] = {0.f, 0.f, 0.f, 0.f}, ai[4] = {0.f, 0.f, 0.f, 0.f};

    for (int t0 = 0; t0 < L; t0 += 64) {
        int tc = L - t0 < 64 ? L - t0 : 64;
        __syncthreads();
        for (int i = tid; i < tc * 64; i += 256) {
            int tt = i >> 6, el = i & 63;
            tile[tt][el] = x[((long)(b * L + t0 + tt)) * CKD + ec * 64 + el];
        }
        __syncthreads();
        for (int tt = 0; tt < tc; tt++) {
            float v = tile[tt][eh];
            int t = t0 + tt;
#pragma unroll
            for (int j = 0; j < 4; j++) {
                int xx = xg + j * 4;
                int id = (xx * t) & (L - 1);
                ar[j] += v * twc[id];
                ai[j] -= v * tws[id];
            }
        }
    }
    int e = ec * 8 + (eh >> 3), h = eh & 7;
    float2* dst = F + ((long)((b * 8 + h) * 64 + e)) * 16;
#pragma unroll
    for (int j = 0; j < 4; j++) {
        int xx = xg + j * 4;
        if (xx < m) dst[xx] = make_float2(ar[j], ai[j]);
    }
}

// ---------------------------------------------------------------------------
// attn x2 pairs in one launch: 256 blocks; pair = bid >> 7
// ---------------------------------------------------------------------------
__global__ __launch_bounds__(256) void attn2_kernel(
    const float2* __restrict__ QFs, const float2* __restrict__ KFs,
    float2* __restrict__ OFs,
    const float2* __restrict__ QFd, const float2* __restrict__ KFd,
    float2* __restrict__ OFd, int m)
{
    __shared__ float2 qf[1024], kf[1024], S[256];
    int bh = blockIdx.x & 127, pair = blockIdx.x >> 7;
    int tid = threadIdx.x;
    const float2* QF = pair ? QFd : QFs;
    const float2* KF = pair ? KFd : KFs;
    float2* OF = pair ? OFd : OFs;
    const float2* qsrc = QF + (long)bh * 1024;
    const float2* ksrc = KF + (long)bh * 1024;
    for (int i = tid; i < 1024; i += 256) { qf[i] = qsrc[i]; kf[i] = ksrc[i]; }
    __syncthreads();

    for (int s = tid; s < m * m; s += 256) {
        int xx = s / m, yy = s - xx * m;
        float re = 0.f, im = 0.f;
#pragma unroll 8
        for (int e = 0; e < 64; e++) {
            float2 qv = qf[e * 16 + xx], kv = kf[e * 16 + yy];
            re += qv.x * kv.x - qv.y * kv.y;
            im += qv.x * kv.y + qv.y * kv.x;
        }
        float X = 2.f * re, Y = 2.f * im, orr, oii;
        if (fabsf(X) > 20.f) {
            orr = copysignf(1.f, X); oii = 0.f;
        } else {
            float ex = expf(X), enx = 1.f / ex;
            float sh = 0.5f * (ex - enx), ch = 0.5f * (ex + enx);
            float sy, cy; sincosf(Y, &sy, &cy);
            float den = ch + cy;
            orr = sh / den; oii = sy / den;
        }
        S[xx * 16 + yy] = make_float2(orr, oii);
    }
    __syncthreads();
    for (int o = tid; o < 64 * m; o += 256) {
        int e = o / m, xx = o - e * m;
        float re = 0.f, im = 0.f;
        for (int yy = 0; yy < m; yy++) {
            float2 sv = S[xx * 16 + yy], kv = kf[e * 16 + yy];
            re += sv.x * kv.x - sv.y * kv.y;
            im += sv.x * kv.y + sv.y * kv.x;
        }
        OF[(long)bh * 1024 + e * 16 + xx] = make_float2(re, im);
    }
}

// ---------------------------------------------------------------------------
// irfft x2 in one launch: grid (8, B, 2)
// z=0: US = irfft(OFs);  z=1: UD = irfft(OFs + OFd)   [linearity]
// ---------------------------------------------------------------------------
__global__ __launch_bounds__(256) void irfft2_kernel(
    const float2* __restrict__ OFs, const float2* __restrict__ OFd,
    float* __restrict__ US, float* __restrict__ UD, int L, int m)
{
    __shared__ float twc[512], tws[512];
    __shared__ float2 of_s[64][16];
    int tid = threadIdx.x, ec = blockIdx.x, b = blockIdx.y, z = blockIdx.z;
    float* out = z ? UD : US;

    for (int i = tid; i < L; i += 256) {
        float th = 6.2831853071795864f * (float)i / (float)L;
        float s, c; sincosf(th, &s, &c);
        twc[i] = c; tws[i] = s;
    }
    float inv = 1.f / ((float)L * 4096.f);
    for (int i = tid; i < 1024; i += 256) {
        int el = i >> 4, xx = i & 15;
        int e = ec * 8 + (el >> 3), h = el & 7;
        float2 v = make_float2(0.f, 0.f);
        if (xx < m) {
            long src = ((long)((b * 8 + h) * 64 + e)) * 16 + xx;
            v = OFs[src];
            if (z) { float2 d = OFd[src]; v.x += d.x; v.y += d.y; }
        }
        float w = (xx == 0) ? inv : 2.f * inv;
        of_s[el][xx] = make_float2(v.x * w, v.y * w);
    }
    __syncthreads();

    for (long i = tid; i < (long)L * 64; i += 256) {
        int el = (int)(i & 63);
        int t = (int)(i >> 6);
        float acc = 0.f;
#pragma unroll
        for (int xx = 0; xx < 16; xx++) {
            int id = (xx * t) & (L - 1);
            float2 f = of_s[el][xx];
            acc += f.x * twc[id] - f.y * tws[id];
        }
        long dst = ((long)(b * L + t)) * CKD + ec * 64 + el;
        out[dst] = acc;
    }
}

__global__ void zero2_kernel(float* p0, float* p1, long n) {
    long i = (long)blockIdx.x * blockDim.x + threadIdx.x;
    if (i < n) { p0[i] = 0.f; p1[i] = 0.f; }
}

// ---------------------------------------------------------------------------
extern "C" void kernel_launch(void* const* d_in, const int* in_sizes, int n_in,
                              void* d_out, int out_size)
{
    const float* q    = (const float*)d_in[0];
    const float* k    = (const float*)d_in[1];
    const float* Lq_w = (const float*)d_in[3];
    const float* Lq_b = (const float*)d_in[4];
    const float* Lk_w = (const float*)d_in[5];
    const float* Lk_b = (const float*)d_in[6];
    const float* out_w = (const float*)d_in[9];
    const float* out_b = (const float*)d_in[10];
    const float* ec_s = (const float*)d_in[11];
    const float* ec_d = (const float*)d_in[12];
    const float* rc_e = (const float*)d_in[13];
    const float* rc_o = (const float*)d_in[14];

    float *QA, *QB, *KA, *KB, *DQ, *DK, *US, *UD, *VA, *VB;
    float2 *QFs, *KFs, *QFd, *KFd, *OFs, *OFd;
    __nv_bfloat16 *Ah, *Al, *Ah2, *Al2, *Wh0, *Wl0, *Wh1, *Wl1, *Wh2, *Wl2;
    cudaGetSymbolAddress((void**)&QA, g_QA);
    cudaGetSymbolAddress((void**)&QB, g_QB);
    cudaGetSymbolAddress((void**)&KA, g_KA);
    cudaGetSymbolAddress((void**)&KB, g_KB);
    cudaGetSymbolAddress((void**)&DQ, g_DQ);
    cudaGetSymbolAddress((void**)&DK, g_DK);
    cudaGetSymbolAddress((void**)&US, g_US);
    cudaGetSymbolAddress((void**)&UD, g_UD);
    cudaGetSymbolAddress((void**)&VA, g_VA);
    cudaGetSymbolAddress((void**)&VB, g_VB);
    cudaGetSymbolAddress((void**)&QFs, g_QFs);
    cudaGetSymbolAddress((void**)&KFs, g_KFs);
    cudaGetSymbolAddress((void**)&QFd, g_QFd);
    cudaGetSymbolAddress((void**)&KFd, g_KFd);
    cudaGetSymbolAddress((void**)&OFs, g_OFs);
    cudaGetSymbolAddress((void**)&OFd, g_OFd);
    cudaGetSymbolAddress((void**)&Ah, g_Ah);
    cudaGetSymbolAddress((void**)&Al, g_Al);
    cudaGetSymbolAddress((void**)&Ah2, g_Ah2);
    cudaGetSymbolAddress((void**)&Al2, g_Al2);
    cudaGetSymbolAddress((void**)&Wh0, g_Wh0);
    cudaGetSymbolAddress((void**)&Wl0, g_Wl0);
    cudaGetSymbolAddress((void**)&Wh1, g_Wh1);
    cudaGetSymbolAddress((void**)&Wl1, g_Wl1);
    cudaGetSymbolAddress((void**)&Wh2, g_Wh2);
    cudaGetSymbolAddress((void**)&Wl2, g_Wl2);

    cudaFuncSetAttribute(gemm_bf16x3,
                         cudaFuncAttributeMaxDynamicSharedMemorySize,
                         GSMEM_BYTES);
    cudaFuncSetAttribute(gemm_bf16x3_dual,
                         cudaFuncAttributeMaxDynamicSharedMemorySize,
                         GSMEM_BYTES);

    // weight splits (all three) + input splits (q,k) + dual projection GEMM
    split_wt3_kernel<<<dim3(16, 16, 3), dim3(32, 8)>>>(
        Lq_w, Lk_w, out_w, Wh0, Wl0, Wh1, Wl1, Wh2, Wl2);
    split_a2_kernel<<<dim3(8192, 2), 256>>>(q, k, Ah, Al, Ah2, Al2, 2097152);
    gemm_bf16x3_dual<<<dim3(4, 128, 2), 256, GSMEM_BYTES>>>(
        Ah, Al, Wh0, Wl0, Lq_b, QA,
        Ah2, Al2, Wh1, Wl1, Lk_b, KA);

    float* qc = QA; float* qn = QB;
    float* kc = KA; float* kn = KB;
    long offs[10]; int Lhs[10];
    long off = 0;
    int L = 1024;
    for (int i = 0; i < 10; i++) {
        int Lh = L >> 1;
        Lhs[i] = Lh; offs[i] = off;
        off += (long)BB * Lh * CKD;
        int m = (Lh / 2 < 16) ? (Lh / 2) : 16;
        long total = (long)BB * Lh * 64;
        int blocks = (int)((total + 255) / 256);

        wavelet2_kernel<<<dim3(blocks, 2), 256>>>(
            qc, kc, ec_d, ec_s, DQ, qn, DK, kn, Lh);

        long sz = (long)BB * Lh * CKD;
        if (m > 0) {
            rfft4_kernel<<<dim3(8, BB, 4), 256>>>(
                DQ, DK, qn, kn, QFs, KFs, QFd, KFd, Lh, m);
            attn2_kernel<<<256, 256>>>(QFs, KFs, OFs, QFd, KFd, OFd, m);
            irfft2_kernel<<<dim3(8, BB, 2), 256>>>(
                OFs, OFd, US + offs[i], UD + offs[i], Lh, m);
        } else {
            zero2_kernel<<<(int)((sz + 255) / 256), 256>>>(
                US + offs[i], UD + offs[i], sz);
        }
        { float* t = qc; qc = qn; qn = t; }
        { float* t = kc; kc = kn; kn = t; }
        L = Lh;
    }

    zero2_kernel<<<32, 256>>>(VA, VA, (long)BB * 1 * CKD);
    float* vc = VA; float* vn = VB;
    for (int i = 9; i >= 0; i--) {
        int Lv = Lhs[i];
        long total = (long)BB * Lv * 64;
        recon_kernel<<<(int)((total + 255) / 256), 256>>>(
            vc, US + offs[i], UD + offs[i], rc_e, rc_o, vn, Lv,
            Ah, Al, (i == 0) ? 1 : 0);
        float* t = vc; vc = vn; vn = t;
    }

    // Output projection (recon already emitted the bf16 split into Ah/Al)
    gemm_bf16x3<<<dim3(4, 128), 256, GSMEM_BYTES>>>(
        Ah, Al, Wh2, Wl2, out_b, (float*)d_out);
}